// round 15
// baseline (speedup 1.0000x reference)
#include <cuda_runtime.h>
#include <cuda_bf16.h>
#include <mma.h>
#include <math.h>
#include <stdint.h>

using namespace nvcuda;

#define HW  16384
#define RST 20736           // 16*16*81
#define MV  400
#define GDS (128*144)

__device__ float g_R[64 * RST];
__device__ float g_P[64 * MV];
__device__ float g_dA[32 * MV];
__device__ float g_dB[32 * MV];
__device__ float g_D[2 * 64 * GDS];                       // [half][s][128][144]
__device__ __nv_bfloat16 g_PBhi[64 * 16 * 128 * 144];     // col-padded planes
__device__ __nv_bfloat16 g_PBlo[64 * 16 * 128 * 144];     // x[g][c-8], c in [0,144)

__device__ __forceinline__ uint32_t s2u(const void* p){
    uint32_t a;
    asm("{ .reg .u64 t; cvta.to.shared.u64 t, %1; cvt.u32.u64 %0, t; }" : "=r"(a) : "l"(p));
    return a;
}

// ---------------- convert: x -> bf16 hi/lo col-padded planes -----------------
// PB[s][j][g][c] = x_j[g][c-8] (c-8 in [0,128)), pads zero. hi = truncate16(x).
__global__ __launch_bounds__(256) void convert_kernel(const float* __restrict__ x1,
                                                      const float* __restrict__ x2)
{
    const int s = blockIdx.x, j = blockIdx.y;
    const float* xr = ((s < 32) ? x1 + (size_t)s * 16 * HW
                                : x2 + (size_t)(s - 32) * 16 * HW) + (size_t)j * HW;
    __nv_bfloat16* PH = g_PBhi + (size_t)(s * 16 + j) * 128 * 144;
    __nv_bfloat16* PL = g_PBlo + (size_t)(s * 16 + j) * 128 * 144;
    for (int idx = threadIdx.x; idx < 128 * 18; idx += 256) {
        const int g = idx / 18, cu = idx % 18;
        if (cu == 0) {
            *(uint4*)(PH + g * 144) = make_uint4(0, 0, 0, 0);
            *(uint4*)(PL + g * 144) = make_uint4(0, 0, 0, 0);
        } else if (cu == 17) {
            *(uint4*)(PH + g * 144 + 136) = make_uint4(0, 0, 0, 0);
            *(uint4*)(PL + g * 144 + 136) = make_uint4(0, 0, 0, 0);
        } else {
            const int w0 = (cu - 1) * 8;
            float4 v0 = *(const float4*)(xr + g * 128 + w0);
            float4 v1 = *(const float4*)(xr + g * 128 + w0 + 4);
            float f[8] = { v0.x, v0.y, v0.z, v0.w, v1.x, v1.y, v1.z, v1.w };
            uint32_t hh[4], ll[4];
#pragma unroll
            for (int q = 0; q < 4; q++) {
                uint32_t ua = __float_as_uint(f[2 * q]);
                uint32_t ub = __float_as_uint(f[2 * q + 1]);
                hh[q] = __byte_perm(ua, ub, 0x7632);
                float la = f[2 * q]     - __uint_as_float(ua & 0xffff0000u);
                float lb = f[2 * q + 1] - __uint_as_float(ub & 0xffff0000u);
                __nv_bfloat162 t = __floats2bfloat162_rn(la, lb);
                ll[q] = *reinterpret_cast<uint32_t*>(&t);
            }
            *(uint4*)(PH + g * 144 + 8 + w0) = make_uint4(hh[0], hh[1], hh[2], hh[3]);
            *(uint4*)(PL + g * 144 + 8 + w0) = make_uint4(ll[0], ll[1], ll[2], ll[3]);
        }
    }
}

// ---------------- autocorr GEMM: CTA = (half, sample) ------------------------
// D[u*16+i][v*16+j] = sum_{g in half, w} x_i[g+4-u, w] * x_j[g, w+v-4]
// smem: Ahi/Alo [128][128] bf16, Bhi/Blo [144][128] bf16 (139264 B)
#define SMA_HI 0
#define SMA_LO 32768
#define SMB_HI 65536
#define SMB_LO 102400
#define SMG_TOT 139264

__global__ __launch_bounds__(384, 1) void gemm_kernel()
{
    extern __shared__ char sm[];
    __nv_bfloat16* Ahi = (__nv_bfloat16*)(sm + SMA_HI);
    __nv_bfloat16* Alo = (__nv_bfloat16*)(sm + SMA_LO);
    __nv_bfloat16* Bhi = (__nv_bfloat16*)(sm + SMB_HI);
    __nv_bfloat16* Blo = (__nv_bfloat16*)(sm + SMB_LO);
    const uint32_t sb = s2u(sm);

    const int s = blockIdx.y, half = blockIdx.x;
    const int tid = threadIdx.x, warp = tid >> 5;
    const int chbase = s * 16;
    const int mg = warp & 3, ng = warp >> 2;     // 4 x 3 warp grid

    wmma::fragment<wmma::accumulator, 16, 16, 16, float> acc[2][3];
#pragma unroll
    for (int a = 0; a < 2; a++)
#pragma unroll
        for (int b = 0; b < 3; b++) wmma::fill_fragment(acc[a][b], 0.0f);

    for (int gs = 0; gs < 64; gs++) {
        const int g = half * 64 + gs;
        // ---- stage A (row shifts) via cp.async, oob rows -> zeros ----
        for (int idx = tid; idx < 4096; idx += 384) {
            const int c16 = idx & 15;
            const int m   = (idx >> 4) & 127;
            const int pl  = idx >> 11;
            const int r = g + 4 - (m >> 4);
            const uint32_t dst = sb + (pl ? SMA_LO : SMA_HI) + m * 256 + c16 * 16;
            if (r >= 0 && r < 128) {
                const __nv_bfloat16* src = (pl ? g_PBlo : g_PBhi)
                    + ((size_t)(chbase + (m & 15)) * 128 + r) * 144 + 8 + c16 * 8;
                asm volatile("cp.async.cg.shared.global [%0], [%1], 16;"
                             :: "r"(dst), "l"(src));
            } else {
                asm volatile("st.shared.v4.u32 [%0], {%1,%1,%1,%1};"
                             :: "r"(dst), "r"(0u));
            }
        }
        asm volatile("cp.async.commit_group;");
        // ---- stage B (col shifts) via u32 funnel ----
        for (int idx = tid; idx < 2304; idx += 384) {   // 144 n x 8 grp x 2 pl
            const int gp = idx & 7;
            const int n  = (idx >> 3) % 144;
            const int pl = idx / 1152;
            const int v = n >> 4, j = n & 15;
            const uint32_t* U = (const uint32_t*)((pl ? g_PBlo : g_PBhi)
                + ((size_t)(chbase + j) * 128 + g) * 144);
            const int a0 = ((v + 4) >> 1) + gp * 8;
            uint32_t o[8];
            if ((v & 1) == 0) {
#pragma unroll
                for (int t = 0; t < 8; t++) o[t] = U[a0 + t];
            } else {
                uint32_t prev = U[a0];
#pragma unroll
                for (int t = 0; t < 8; t++) {
                    uint32_t nx = U[a0 + t + 1];
                    o[t] = __funnelshift_r(prev, nx, 16);
                    prev = nx;
                }
            }
            char* dst = sm + (pl ? SMB_LO : SMB_HI) + n * 256 + gp * 32;
            *(uint4*)dst       = make_uint4(o[0], o[1], o[2], o[3]);
            *(uint4*)(dst + 16) = make_uint4(o[4], o[5], o[6], o[7]);
        }
        asm volatile("cp.async.wait_group 0;");
        __syncthreads();

        // ---- compute: 8 k-chunks, warp tile 2m x 3n, 3 split passes ----
#pragma unroll 1
        for (int kc = 0; kc < 8; kc++) {
            const int ko = kc * 16;
            wmma::fragment<wmma::matrix_a, 16, 16, 16, __nv_bfloat16, wmma::row_major> ah[2], al[2];
            wmma::fragment<wmma::matrix_b, 16, 16, 16, __nv_bfloat16, wmma::col_major> bh[3], bl;
#pragma unroll
            for (int t = 0; t < 2; t++) {
                wmma::load_matrix_sync(ah[t], Ahi + (mg * 2 + t) * 16 * 128 + ko, 128);
                wmma::load_matrix_sync(al[t], Alo + (mg * 2 + t) * 16 * 128 + ko, 128);
            }
#pragma unroll
            for (int t = 0; t < 3; t++)
                wmma::load_matrix_sync(bh[t], Bhi + (ng * 3 + t) * 16 * 128 + ko, 128);
#pragma unroll
            for (int a = 0; a < 2; a++)
#pragma unroll
                for (int b = 0; b < 3; b++) wmma::mma_sync(acc[a][b], ah[a], bh[b], acc[a][b]);
#pragma unroll
            for (int b = 0; b < 3; b++) {
                wmma::load_matrix_sync(bl, Blo + (ng * 3 + b) * 16 * 128 + ko, 128);
#pragma unroll
                for (int a = 0; a < 2; a++) wmma::mma_sync(acc[a][b], ah[a], bl, acc[a][b]);
            }
#pragma unroll
            for (int a = 0; a < 2; a++)
#pragma unroll
                for (int b = 0; b < 3; b++) wmma::mma_sync(acc[a][b], al[a], bh[b], acc[a][b]);
        }
        __syncthreads();
    }

    float* dst = g_D + (size_t)(half * 64 + s) * GDS;
#pragma unroll
    for (int a = 0; a < 2; a++)
#pragma unroll
        for (int b = 0; b < 3; b++)
            wmma::store_matrix_sync(dst + (mg * 2 + a) * 16 * 144 + (ng * 3 + b) * 16,
                                    acc[a][b], 144, wmma::mem_row_major);
}

// ---------------- fill: sum 2 half-partials -> g_R, mirror u=8 ---------------
__global__ __launch_bounds__(256) void fill_kernel()
{
    const int s = blockIdx.x, t = threadIdx.x;
    const float* D0 = g_D + (size_t)s * GDS;
    const float* D1 = g_D + (size_t)(64 + s) * GDS;
    for (int idx = t; idx < RST; idx += 256) {
        const int pair = idx / 81, lag = idx - pair * 81;
        const int i = pair >> 4, j = pair & 15, u = lag / 9, v = lag - u * 9;
        int m, n;
        if (u < 8) { m = u * 16 + i; n = v * 16 + j; }
        else       { m = j;          n = (8 - v) * 16 + i; }  // R[i,j,8,v]=R[j,i,0,8-v]
        g_R[(size_t)s * RST + idx] = D0[m * 144 + n] + D1[m * 144 + n];
    }
}

// ---------------- crosscorr: CTA = (channel j, sample s) ---------------------
__global__ __launch_bounds__(160) void crosscorr_kernel(const float* __restrict__ x1,
                                                        const float* __restrict__ x2,
                                                        const float* __restrict__ y1,
                                                        const float* __restrict__ y2)
{
    extern __shared__ float smf[];
    float* ys = smf;
    float* xs = smf + 16384;
    const int s = blockIdx.y, j = blockIdx.x;
    const float* x = (s < 32) ? (x1 + (size_t)s * 16 * HW) : (x2 + (size_t)(s - 32) * 16 * HW);
    const float* y = (s < 32) ? (y1 + (size_t)s * HW) : (y2 + (size_t)(s - 32) * HW);
    const int tid = threadIdx.x;
    {
        for (int k = tid; k < HW / 4; k += 160) ((float4*)ys)[k] = ((const float4*)y)[k];
        const float* gx = x + (size_t)j * HW;
        for (int k = tid; k < 128 * 34; k += 160) {
            int r = k / 34, w0 = (k % 34) * 4 - 4;
            float t0 = (w0 >= 0 && w0 < 128)         ? gx[r * 128 + w0]     : 0.f;
            float t1 = (w0 + 1 >= 0 && w0 + 1 < 128) ? gx[r * 128 + w0 + 1] : 0.f;
            float t2 = (w0 + 2 >= 0 && w0 + 2 < 128) ? gx[r * 128 + w0 + 2] : 0.f;
            float t3 = (w0 + 3 >= 0 && w0 + 3 < 128) ? gx[r * 128 + w0 + 3] : 0.f;
            ((float4*)xs)[k] = make_float4(t0, t1, t2, t3);
        }
    }
    __syncthreads();
    const int warp = tid >> 5, lane = tid & 31;
    const int du = warp - 2, w0 = lane << 2;
    float acc[5] = {0.f, 0.f, 0.f, 0.f, 0.f};
    const int hbeg = (du < 0) ? -du : 0;
    const int hend = (du > 0) ? 128 - du : 128;
    const float* py = ys + hbeg * 128 + w0;
    const float* px = xs + (hbeg + du) * 136 + w0;
    for (int h = hbeg; h < hend; h++) {
        const float4 av = *(const float4*)py;
        const float4 b0 = *(const float4*)px;
        const float4 b1 = *(const float4*)(px + 4);
        const float4 b2 = *(const float4*)(px + 8);
        const float bb[12] = { b0.x, b0.y, b0.z, b0.w, b1.x, b1.y, b1.z, b1.w,
                               b2.x, b2.y, b2.z, b2.w };
#pragma unroll
        for (int t = 0; t < 5; t++) {
            acc[t] = fmaf(av.x, bb[t + 2], acc[t]);
            acc[t] = fmaf(av.y, bb[t + 3], acc[t]);
            acc[t] = fmaf(av.z, bb[t + 4], acc[t]);
            acc[t] = fmaf(av.w, bb[t + 5], acc[t]);
        }
        py += 128; px += 136;
    }
#pragma unroll
    for (int t = 0; t < 5; t++) {
        float v = acc[t];
#pragma unroll
        for (int o = 16; o; o >>= 1) v += __shfl_down_sync(0xffffffffu, v, o);
        if (lane == 0) g_P[(size_t)s * MV + j * 25 + warp * 5 + t] = v;
    }
}

// ---------------- CG solve from R (Q never materialized) ---------------------
__device__ __forceinline__ float dot400(const float* A, const float* B, float* scr, int t)
{
    float v = 0.f;
    for (int k = t; k < MV; k += 256) v += A[k] * B[k];
#pragma unroll
    for (int o = 16; o; o >>= 1) v += __shfl_down_sync(0xffffffffu, v, o);
    if ((t & 31) == 0) scr[t >> 5] = v;
    __syncthreads();
    if (t < 32) {
        float w = (t < 8) ? scr[t] : 0.f;
#pragma unroll
        for (int o = 4; o; o >>= 1) w += __shfl_down_sync(0xffffffffu, w, o);
        if (t == 0) scr[0] = w;
    }
    __syncthreads();
    float r = scr[0];
    __syncthreads();
    return r;
}

__global__ __launch_bounds__(256) void cg_kernel(int soff, const float* __restrict__ dprev,
                                                 const float* __restrict__ alpha,
                                                 const float* __restrict__ reg,
                                                 float* __restrict__ dout)
{
    extern __shared__ float smf[];
    float* Rs  = smf;
    float* red = Rs + RST;
    float* vx  = red + 16 * MV;
    float* vr  = vx + MV;
    float* vp  = vr + MV;
    float* vq  = vp + MV;
    float* scr = vq + MV;
    const int s = blockIdx.x, t = threadIdx.x;
    const float a = alpha[s] * 16384.f * reg[0] / 400.f;

    {
        const float4* gr = (const float4*)(g_R + (size_t)(s + soff) * RST);
        for (int k = t; k < RST / 4; k += 256) ((float4*)Rs)[k] = gr[k];
    }
    for (int k = t; k < MV; k += 256) {
        float b = g_P[(size_t)(s + soff) * MV + k] + a * dprev[(size_t)s * MV + k];
        vr[k] = b; vp[k] = b; vx[k] = 0.f;
    }
    __syncthreads();
    float rs = dot400(vr, vr, scr, t);

    const int jj = t & 15;
    const float* Rb = Rs + t * 81;

    for (int it = 0; it < 14; it++) {
        float vj[25];
#pragma unroll
        for (int o = 0; o < 25; o++) vj[o] = vp[jj * 25 + o];
        float acc[25];
#pragma unroll
        for (int o = 0; o < 25; o++) acc[o] = 0.f;
#pragma unroll
        for (int oi = 0; oi < 5; oi++)
#pragma unroll
            for (int oj = 0; oj < 5; oj++) {
                const float v = vj[oi * 5 + oj];
#pragma unroll
                for (int p = 0; p < 5; p++)
#pragma unroll
                    for (int q = 0; q < 5; q++)
                        acc[p * 5 + q] = fmaf(Rb[(4 + oi - p) * 9 + (4 + oj - q)], v, acc[p * 5 + q]);
            }
#pragma unroll
        for (int o = 0; o < 25; o++) red[jj * MV + (t >> 4) * 25 + o] = acc[o];
        __syncthreads();
        for (int k = t; k < MV; k += 256) {
            float ssum = a * vp[k];
#pragma unroll
            for (int j2 = 0; j2 < 16; j2++) ssum += red[j2 * MV + k];
            vq[k] = ssum;
        }
        __syncthreads();
        float pq = dot400(vp, vq, scr, t);
        float al = rs / pq;
        for (int k = t; k < MV; k += 256) { vx[k] += al * vp[k]; vr[k] -= al * vq[k]; }
        __syncthreads();
        float rs2 = dot400(vr, vr, scr, t);
        float be = rs2 / rs;
        rs = rs2;
        for (int k = t; k < MV; k += 256) vp[k] = vr[k] + be * vp[k];
        __syncthreads();
    }
    for (int k = t; k < MV; k += 256) dout[(size_t)s * MV + k] = vx[k];
}

// ---------------- conv head: 6 x conv3x3(pad1) on 5x5 maps -------------------
__device__ __forceinline__ void conv5(float* outb, const float* inb, const float* w,
                                      const float* bias, int cin, int doRelu, int t)
{
    if (t < MV) {
        const int oc = t / 25, pos = t % 25, p = pos / 5, q = pos % 5;
        float v = bias[oc];
        for (int ic = 0; ic < cin; ic++) {
            const float* wp = w + (oc * cin + ic) * 9;
            const float* ip = inb + ic * 25;
#pragma unroll
            for (int kh = 0; kh < 3; kh++) {
                int r = p + kh - 1;
                if (r < 0 || r > 4) continue;
#pragma unroll
                for (int kw = 0; kw < 3; kw++) {
                    int c = q + kw - 1;
                    if (c < 0 || c > 4) continue;
                    v = fmaf(wp[kh * 3 + kw], ip[r * 5 + c], v);
                }
            }
        }
        outb[t] = doRelu ? fmaxf(v, 0.f) : v;
    }
    __syncthreads();
}

__global__ __launch_bounds__(400) void head_kernel(const float* __restrict__ beta,
    const float* w1, const float* b1, const float* w2, const float* b2,
    const float* w3, const float* b3, const float* w4, const float* b4,
    const float* w5, const float* b5, const float* w6, const float* b6,
    float* __restrict__ out)
{
    __shared__ float h0[17 * 25], bA[16 * 25], bB[16 * 25];
    const int s = blockIdx.x, t = threadIdx.x;
    if (t < MV) h0[t] = g_dB[(size_t)s * MV + t];
    if (t < 25) h0[MV + t] = 1.0f / sqrtf(beta[s]);
    __syncthreads();
    conv5(bA, h0, w1, b1, 17, 1, t);
    conv5(bB, bA, w2, b2, 16, 1, t);
    conv5(bA, bB, w3, b3, 16, 1, t);
    conv5(bB, bA, w4, b4, 16, 1, t);
    conv5(bA, bB, w5, b5, 16, 1, t);
    if (t < MV) {
        const int oc = t / 25, pos = t % 25, p = pos / 5, q = pos % 5;
        float v = b6[oc];
        for (int ic = 0; ic < 16; ic++) {
            const float* wp = w6 + (oc * 16 + ic) * 9;
            const float* ip = bA + ic * 25;
#pragma unroll
            for (int kh = 0; kh < 3; kh++) {
                int r = p + kh - 1;
                if (r < 0 || r > 4) continue;
#pragma unroll
                for (int kw = 0; kw < 3; kw++) {
                    int c = q + kw - 1;
                    if (c < 0 || c > 4) continue;
                    v = fmaf(wp[kh * 3 + kw], ip[r * 5 + c], v);
                }
            }
        }
        out[(size_t)s * MV + t] = v + h0[t];
    }
}

extern "C" void kernel_launch(void* const* d_in, const int* in_sizes, int n_in,
                              void* d_out, int out_size)
{
    const float* x1 = (const float*)d_in[0];
    const float* x2 = (const float*)d_in[1];
    const float* d  = (const float*)d_in[2];
    const float* y1 = (const float*)d_in[3];
    const float* y2 = (const float*)d_in[4];
    const float* alpha = (const float*)d_in[5];
    const float* beta  = (const float*)d_in[6];
    const float* reg   = (const float*)d_in[7];
    const float* w1 = (const float*)d_in[8];  const float* b1 = (const float*)d_in[9];
    const float* w2 = (const float*)d_in[10]; const float* b2 = (const float*)d_in[11];
    const float* w3 = (const float*)d_in[12]; const float* b3 = (const float*)d_in[13];
    const float* w4 = (const float*)d_in[14]; const float* b4 = (const float*)d_in[15];
    const float* w5 = (const float*)d_in[16]; const float* b5 = (const float*)d_in[17];
    const float* w6 = (const float*)d_in[18]; const float* b6 = (const float*)d_in[19];

    const int SM_CC = 33792 * 4;
    const int SM_CG = (RST + 16 * MV + 4 * MV + 256) * 4;

    cudaFuncSetAttribute(gemm_kernel,      cudaFuncAttributeMaxDynamicSharedMemorySize, SMG_TOT);
    cudaFuncSetAttribute(crosscorr_kernel, cudaFuncAttributeMaxDynamicSharedMemorySize, SM_CC);
    cudaFuncSetAttribute(cg_kernel,        cudaFuncAttributeMaxDynamicSharedMemorySize, SM_CG);

    float* dA; cudaGetSymbolAddress((void**)&dA, g_dA);
    float* dB; cudaGetSymbolAddress((void**)&dB, g_dB);

    dim3 gv(64, 16);
    convert_kernel<<<gv, 256>>>(x1, x2);
    dim3 gg(2, 64);
    gemm_kernel<<<gg, 384, SMG_TOT>>>();
    dim3 gc(16, 64);
    crosscorr_kernel<<<gc, 160, SM_CC>>>(x1, x2, y1, y2);
    fill_kernel<<<64, 256>>>();
    cg_kernel<<<32, 256, SM_CG>>>(0, d, alpha, reg, dA);
    cg_kernel<<<32, 256, SM_CG>>>(32, dA, alpha, reg, dB);
    head_kernel<<<32, 400>>>(beta, w1, b1, w2, b2, w3, b3, w4, b4, w5, b5, w6, b6,
                             (float*)d_out);
}

// round 16
// speedup vs baseline: 1.1777x; 1.1777x over previous
#include <cuda_runtime.h>
#include <cuda_bf16.h>
#include <mma.h>
#include <math.h>
#include <stdint.h>

using namespace nvcuda;

#define HW  16384
#define RST 20736           // 16*16*81
#define MV  400
#define GDS (128*144)

__device__ float g_R[64 * RST];
__device__ float g_P[64 * MV];
__device__ float g_dA[32 * MV];
__device__ float g_dB[32 * MV];
__device__ float g_D[2 * 64 * GDS];                     // [half][s][128][144]
__device__ __nv_bfloat16 g_PBhi[64 * 16 * 128 * 128];   // [s][ch][g][w] hi
__device__ __nv_bfloat16 g_PBlo[64 * 16 * 128 * 128];   // lo

// ---------------- convert: x -> bf16 hi/lo planes (unpadded) -----------------
__global__ __launch_bounds__(256) void convert_kernel(const float* __restrict__ x1,
                                                      const float* __restrict__ x2)
{
    const int s = blockIdx.x, j = blockIdx.y;
    const float* xr = ((s < 32) ? x1 + (size_t)s * 16 * HW
                                : x2 + (size_t)(s - 32) * 16 * HW) + (size_t)j * HW;
    __nv_bfloat16* PH = g_PBhi + (size_t)(s * 16 + j) * HW;
    __nv_bfloat16* PL = g_PBlo + (size_t)(s * 16 + j) * HW;
    for (int idx = threadIdx.x; idx < 2048; idx += 256) {   // 2048 uint4 = 16384 bf16
        const int e0 = idx * 8;
        float4 v0 = *(const float4*)(xr + e0);
        float4 v1 = *(const float4*)(xr + e0 + 4);
        float f[8] = { v0.x, v0.y, v0.z, v0.w, v1.x, v1.y, v1.z, v1.w };
        uint32_t hh[4], ll[4];
#pragma unroll
        for (int q = 0; q < 4; q++) {
            uint32_t ua = __float_as_uint(f[2 * q]);
            uint32_t ub = __float_as_uint(f[2 * q + 1]);
            hh[q] = __byte_perm(ua, ub, 0x7632);
            float la = f[2 * q]     - __uint_as_float(ua & 0xffff0000u);
            float lb = f[2 * q + 1] - __uint_as_float(ub & 0xffff0000u);
            __nv_bfloat162 t = __floats2bfloat162_rn(la, lb);
            ll[q] = *reinterpret_cast<uint32_t*>(&t);
        }
        *(uint4*)(PH + e0) = make_uint4(hh[0], hh[1], hh[2], hh[3]);
        *(uint4*)(PL + e0) = make_uint4(ll[0], ll[1], ll[2], ll[3]);
    }
}

// ---------------- autocorr GEMM with smem row-ring ---------------------------
// CTA = (half, sample). D[u*16+i][v*16+j] = sum_{g in half, w} x_i[g+4-u,w]*x_j[g,w+v-4]
// ring: 12 slots x [16 ch][160 cols] bf16 (16 zero pad cols each side), hi+lo.
// B tiles [144][128] hi/lo built per step by u32 funnel from ring row g.
#define RSL 2560                    // ring slot stride in elements (16*160)
#define SM_RH 0
#define SM_RL 61440
#define SM_BH 122880
#define SM_BL 159744
#define SM_TOT 196608

__global__ __launch_bounds__(384, 1) void gemm_kernel()
{
    extern __shared__ char sm[];
    __nv_bfloat16* ringH = (__nv_bfloat16*)(sm + SM_RH);
    __nv_bfloat16* ringL = (__nv_bfloat16*)(sm + SM_RL);
    __nv_bfloat16* Bhi   = (__nv_bfloat16*)(sm + SM_BH);
    __nv_bfloat16* Blo   = (__nv_bfloat16*)(sm + SM_BL);

    const int s = blockIdx.y, half = blockIdx.x, h0 = half * 64;
    const int tid = threadIdx.x, warp = tid >> 5;
    const int mg = warp & 3, ng = warp >> 2;           // 4 x 3 warp grid
    const __nv_bfloat16* PH = g_PBhi + (size_t)s * 16 * HW;
    const __nv_bfloat16* PL = g_PBlo + (size_t)s * 16 * HW;

    // zero pad columns (0..15, 144..159) of all 12 slots, both planes
    for (int idx = tid; idx < 768; idx += 384) {
        int sc = idx >> 2, q = idx & 3;
        int slot = sc / 16, ch = sc % 16;
        int cb = (q < 2) ? q * 8 : 144 + (q - 2) * 8;
        *(uint4*)(ringH + slot * RSL + ch * 160 + cb) = make_uint4(0, 0, 0, 0);
        *(uint4*)(ringL + slot * RSL + ch * 160 + cb) = make_uint4(0, 0, 0, 0);
    }

    auto load_row = [&](int r) {
        const int slot = ((r % 12) + 12) % 12;
        for (int idx = tid; idx < 512; idx += 384) {
            const int pl = idx >> 8, k = idx & 255;
            const int ch = k >> 4, c8 = k & 15;
            uint4 v = make_uint4(0, 0, 0, 0);
            if (r >= 0 && r < 128)
                v = *(const uint4*)((pl ? PL : PH) + ((size_t)ch * 128 + r) * 128 + c8 * 8);
            *(uint4*)((pl ? ringL : ringH) + slot * RSL + ch * 160 + 16 + c8 * 8) = v;
        }
    };

    for (int r = h0 - 3; r <= h0 + 3; r++) load_row(r);
    __syncthreads();

    wmma::fragment<wmma::accumulator, 16, 16, 16, float> acc[2][3];
#pragma unroll
    for (int a = 0; a < 2; a++)
#pragma unroll
        for (int b = 0; b < 3; b++) wmma::fill_fragment(acc[a][b], 0.0f);

    for (int gs = 0; gs < 64; gs++) {
        const int g = h0 + gs;
        load_row(g + 4);
        // ---- build B tiles from ring row g (slot g%12) ----
        {
            const int slot = g % 12;
            for (int idx = tid; idx < 2304; idx += 384) {   // 144 n x 8 gp x 2 pl
                const int gp = idx & 7;
                const int n  = (idx >> 3) % 144;
                const int pl = idx / 1152;
                const int v = n >> 4, j = n & 15;
                const uint32_t* U = (const uint32_t*)((pl ? ringL : ringH)
                                      + slot * RSL + j * 160);
                uint32_t o[8];
                if ((v & 1) == 0) {
                    const int a0 = ((12 + v) >> 1) + gp * 8;
#pragma unroll
                    for (int t = 0; t < 8; t++) o[t] = U[a0 + t];
                } else {
                    const int a0 = ((11 + v) >> 1) + gp * 8;
                    uint32_t prev = U[a0];
#pragma unroll
                    for (int t = 0; t < 8; t++) {
                        uint32_t nx = U[a0 + t + 1];
                        o[t] = __funnelshift_r(prev, nx, 16);
                        prev = nx;
                    }
                }
                char* dst = (char*)(pl ? Blo : Bhi) + n * 256 + gp * 32;
                *(uint4*)dst        = make_uint4(o[0], o[1], o[2], o[3]);
                *(uint4*)(dst + 16) = make_uint4(o[4], o[5], o[6], o[7]);
            }
        }
        __syncthreads();

        // ---- compute: A frags straight from ring, 8 k-chunks ----
#pragma unroll 1
        for (int kc = 0; kc < 8; kc++) {
            const int ko = kc * 16;
            wmma::fragment<wmma::matrix_a, 16, 16, 16, __nv_bfloat16, wmma::row_major> ah[2], al[2];
            wmma::fragment<wmma::matrix_b, 16, 16, 16, __nv_bfloat16, wmma::col_major> bh[3], bl;
#pragma unroll
            for (int t = 0; t < 2; t++) {
                const int u = mg * 2 + t;
                const int slot = (g + 16 - u) % 12;       // row g+4-u
                wmma::load_matrix_sync(ah[t], ringH + slot * RSL + 16 + ko, 160);
                wmma::load_matrix_sync(al[t], ringL + slot * RSL + 16 + ko, 160);
            }
#pragma unroll
            for (int t = 0; t < 3; t++)
                wmma::load_matrix_sync(bh[t], Bhi + (ng * 3 + t) * 16 * 128 + ko, 128);
#pragma unroll
            for (int a = 0; a < 2; a++)
#pragma unroll
                for (int b = 0; b < 3; b++) wmma::mma_sync(acc[a][b], ah[a], bh[b], acc[a][b]);
#pragma unroll
            for (int b = 0; b < 3; b++) {
                wmma::load_matrix_sync(bl, Blo + (ng * 3 + b) * 16 * 128 + ko, 128);
#pragma unroll
                for (int a = 0; a < 2; a++) wmma::mma_sync(acc[a][b], ah[a], bl, acc[a][b]);
            }
#pragma unroll
            for (int a = 0; a < 2; a++)
#pragma unroll
                for (int b = 0; b < 3; b++) wmma::mma_sync(acc[a][b], al[a], bh[b], acc[a][b]);
        }
        __syncthreads();
    }

    float* dst = g_D + (size_t)(half * 64 + s) * GDS;
#pragma unroll
    for (int a = 0; a < 2; a++)
#pragma unroll
        for (int b = 0; b < 3; b++)
            wmma::store_matrix_sync(dst + (mg * 2 + a) * 16 * 144 + (ng * 3 + b) * 16,
                                    acc[a][b], 144, wmma::mem_row_major);
}

// ---------------- fill: sum 2 half-partials -> g_R, mirror u=8 ---------------
__global__ __launch_bounds__(256) void fill_kernel()
{
    const int s = blockIdx.x, t = threadIdx.x;
    const float* D0 = g_D + (size_t)s * GDS;
    const float* D1 = g_D + (size_t)(64 + s) * GDS;
    for (int idx = t; idx < RST; idx += 256) {
        const int pair = idx / 81, lag = idx - pair * 81;
        const int i = pair >> 4, j = pair & 15, u = lag / 9, v = lag - u * 9;
        int m, n;
        if (u < 8) { m = u * 16 + i; n = v * 16 + j; }
        else       { m = j;          n = (8 - v) * 16 + i; }  // R[i,j,8,v]=R[j,i,0,8-v]
        g_R[(size_t)s * RST + idx] = D0[m * 144 + n] + D1[m * 144 + n];
    }
}

// ---------------- crosscorr: CTA = (channel j, sample s) ---------------------
__global__ __launch_bounds__(160) void crosscorr_kernel(const float* __restrict__ x1,
                                                        const float* __restrict__ x2,
                                                        const float* __restrict__ y1,
                                                        const float* __restrict__ y2)
{
    extern __shared__ float smf[];
    float* ys = smf;
    float* xs = smf + 16384;
    const int s = blockIdx.y, j = blockIdx.x;
    const float* x = (s < 32) ? (x1 + (size_t)s * 16 * HW) : (x2 + (size_t)(s - 32) * 16 * HW);
    const float* y = (s < 32) ? (y1 + (size_t)s * HW) : (y2 + (size_t)(s - 32) * HW);
    const int tid = threadIdx.x;
    {
        for (int k = tid; k < HW / 4; k += 160) ((float4*)ys)[k] = ((const float4*)y)[k];
        const float* gx = x + (size_t)j * HW;
        for (int k = tid; k < 128 * 34; k += 160) {
            int r = k / 34, w0 = (k % 34) * 4 - 4;
            float t0 = (w0 >= 0 && w0 < 128)         ? gx[r * 128 + w0]     : 0.f;
            float t1 = (w0 + 1 >= 0 && w0 + 1 < 128) ? gx[r * 128 + w0 + 1] : 0.f;
            float t2 = (w0 + 2 >= 0 && w0 + 2 < 128) ? gx[r * 128 + w0 + 2] : 0.f;
            float t3 = (w0 + 3 >= 0 && w0 + 3 < 128) ? gx[r * 128 + w0 + 3] : 0.f;
            ((float4*)xs)[k] = make_float4(t0, t1, t2, t3);
        }
    }
    __syncthreads();
    const int warp = tid >> 5, lane = tid & 31;
    const int du = warp - 2, w0 = lane << 2;
    float acc[5] = {0.f, 0.f, 0.f, 0.f, 0.f};
    const int hbeg = (du < 0) ? -du : 0;
    const int hend = (du > 0) ? 128 - du : 128;
    const float* py = ys + hbeg * 128 + w0;
    const float* px = xs + (hbeg + du) * 136 + w0;
    for (int h = hbeg; h < hend; h++) {
        const float4 av = *(const float4*)py;
        const float4 b0 = *(const float4*)px;
        const float4 b1 = *(const float4*)(px + 4);
        const float4 b2 = *(const float4*)(px + 8);
        const float bb[12] = { b0.x, b0.y, b0.z, b0.w, b1.x, b1.y, b1.z, b1.w,
                               b2.x, b2.y, b2.z, b2.w };
#pragma unroll
        for (int t = 0; t < 5; t++) {
            acc[t] = fmaf(av.x, bb[t + 2], acc[t]);
            acc[t] = fmaf(av.y, bb[t + 3], acc[t]);
            acc[t] = fmaf(av.z, bb[t + 4], acc[t]);
            acc[t] = fmaf(av.w, bb[t + 5], acc[t]);
        }
        py += 128; px += 136;
    }
#pragma unroll
    for (int t = 0; t < 5; t++) {
        float v = acc[t];
#pragma unroll
        for (int o = 16; o; o >>= 1) v += __shfl_down_sync(0xffffffffu, v, o);
        if (lane == 0) g_P[(size_t)s * MV + j * 25 + warp * 5 + t] = v;
    }
}

// ---------------- CG solve from R (Q never materialized) ---------------------
__device__ __forceinline__ float dot400(const float* A, const float* B, float* scr, int t)
{
    float v = 0.f;
    for (int k = t; k < MV; k += 256) v += A[k] * B[k];
#pragma unroll
    for (int o = 16; o; o >>= 1) v += __shfl_down_sync(0xffffffffu, v, o);
    if ((t & 31) == 0) scr[t >> 5] = v;
    __syncthreads();
    if (t < 32) {
        float w = (t < 8) ? scr[t] : 0.f;
#pragma unroll
        for (int o = 4; o; o >>= 1) w += __shfl_down_sync(0xffffffffu, w, o);
        if (t == 0) scr[0] = w;
    }
    __syncthreads();
    float r = scr[0];
    __syncthreads();
    return r;
}

__global__ __launch_bounds__(256) void cg_kernel(int soff, const float* __restrict__ dprev,
                                                 const float* __restrict__ alpha,
                                                 const float* __restrict__ reg,
                                                 float* __restrict__ dout)
{
    extern __shared__ float smf[];
    float* Rs  = smf;
    float* red = Rs + RST;
    float* vx  = red + 16 * MV;
    float* vr  = vx + MV;
    float* vp  = vr + MV;
    float* vq  = vp + MV;
    float* scr = vq + MV;
    const int s = blockIdx.x, t = threadIdx.x;
    const float a = alpha[s] * 16384.f * reg[0] / 400.f;

    {
        const float4* gr = (const float4*)(g_R + (size_t)(s + soff) * RST);
        for (int k = t; k < RST / 4; k += 256) ((float4*)Rs)[k] = gr[k];
    }
    for (int k = t; k < MV; k += 256) {
        float b = g_P[(size_t)(s + soff) * MV + k] + a * dprev[(size_t)s * MV + k];
        vr[k] = b; vp[k] = b; vx[k] = 0.f;
    }
    __syncthreads();
    float rs = dot400(vr, vr, scr, t);

    const int jj = t & 15;
    const float* Rb = Rs + t * 81;

    for (int it = 0; it < 14; it++) {
        float vj[25];
#pragma unroll
        for (int o = 0; o < 25; o++) vj[o] = vp[jj * 25 + o];
        float acc[25];
#pragma unroll
        for (int o = 0; o < 25; o++) acc[o] = 0.f;
#pragma unroll
        for (int oi = 0; oi < 5; oi++)
#pragma unroll
            for (int oj = 0; oj < 5; oj++) {
                const float v = vj[oi * 5 + oj];
#pragma unroll
                for (int p = 0; p < 5; p++)
#pragma unroll
                    for (int q = 0; q < 5; q++)
                        acc[p * 5 + q] = fmaf(Rb[(4 + oi - p) * 9 + (4 + oj - q)], v, acc[p * 5 + q]);
            }
#pragma unroll
        for (int o = 0; o < 25; o++) red[jj * MV + (t >> 4) * 25 + o] = acc[o];
        __syncthreads();
        for (int k = t; k < MV; k += 256) {
            float ssum = a * vp[k];
#pragma unroll
            for (int j2 = 0; j2 < 16; j2++) ssum += red[j2 * MV + k];
            vq[k] = ssum;
        }
        __syncthreads();
        float pq = dot400(vp, vq, scr, t);
        float al = rs / pq;
        for (int k = t; k < MV; k += 256) { vx[k] += al * vp[k]; vr[k] -= al * vq[k]; }
        __syncthreads();
        float rs2 = dot400(vr, vr, scr, t);
        float be = rs2 / rs;
        rs = rs2;
        for (int k = t; k < MV; k += 256) vp[k] = vr[k] + be * vp[k];
        __syncthreads();
    }
    for (int k = t; k < MV; k += 256) dout[(size_t)s * MV + k] = vx[k];
}

// ---------------- conv head: 6 x conv3x3(pad1) on 5x5 maps -------------------
__device__ __forceinline__ void conv5(float* outb, const float* inb, const float* w,
                                      const float* bias, int cin, int doRelu, int t)
{
    if (t < MV) {
        const int oc = t / 25, pos = t % 25, p = pos / 5, q = pos % 5;
        float v = bias[oc];
        for (int ic = 0; ic < cin; ic++) {
            const float* wp = w + (oc * cin + ic) * 9;
            const float* ip = inb + ic * 25;
#pragma unroll
            for (int kh = 0; kh < 3; kh++) {
                int r = p + kh - 1;
                if (r < 0 || r > 4) continue;
#pragma unroll
                for (int kw = 0; kw < 3; kw++) {
                    int c = q + kw - 1;
                    if (c < 0 || c > 4) continue;
                    v = fmaf(wp[kh * 3 + kw], ip[r * 5 + c], v);
                }
            }
        }
        outb[t] = doRelu ? fmaxf(v, 0.f) : v;
    }
    __syncthreads();
}

__global__ __launch_bounds__(400) void head_kernel(const float* __restrict__ beta,
    const float* w1, const float* b1, const float* w2, const float* b2,
    const float* w3, const float* b3, const float* w4, const float* b4,
    const float* w5, const float* b5, const float* w6, const float* b6,
    float* __restrict__ out)
{
    __shared__ float h0[17 * 25], bA[16 * 25], bB[16 * 25];
    const int s = blockIdx.x, t = threadIdx.x;
    if (t < MV) h0[t] = g_dB[(size_t)s * MV + t];
    if (t < 25) h0[MV + t] = 1.0f / sqrtf(beta[s]);
    __syncthreads();
    conv5(bA, h0, w1, b1, 17, 1, t);
    conv5(bB, bA, w2, b2, 16, 1, t);
    conv5(bA, bB, w3, b3, 16, 1, t);
    conv5(bB, bA, w4, b4, 16, 1, t);
    conv5(bA, bB, w5, b5, 16, 1, t);
    if (t < MV) {
        const int oc = t / 25, pos = t % 25, p = pos / 5, q = pos % 5;
        float v = b6[oc];
        for (int ic = 0; ic < 16; ic++) {
            const float* wp = w6 + (oc * 16 + ic) * 9;
            const float* ip = bA + ic * 25;
#pragma unroll
            for (int kh = 0; kh < 3; kh++) {
                int r = p + kh - 1;
                if (r < 0 || r > 4) continue;
#pragma unroll
                for (int kw = 0; kw < 3; kw++) {
                    int c = q + kw - 1;
                    if (c < 0 || c > 4) continue;
                    v = fmaf(wp[kh * 3 + kw], ip[r * 5 + c], v);
                }
            }
        }
        out[(size_t)s * MV + t] = v + h0[t];
    }
}

extern "C" void kernel_launch(void* const* d_in, const int* in_sizes, int n_in,
                              void* d_out, int out_size)
{
    const float* x1 = (const float*)d_in[0];
    const float* x2 = (const float*)d_in[1];
    const float* d  = (const float*)d_in[2];
    const float* y1 = (const float*)d_in[3];
    const float* y2 = (const float*)d_in[4];
    const float* alpha = (const float*)d_in[5];
    const float* beta  = (const float*)d_in[6];
    const float* reg   = (const float*)d_in[7];
    const float* w1 = (const float*)d_in[8];  const float* b1 = (const float*)d_in[9];
    const float* w2 = (const float*)d_in[10]; const float* b2 = (const float*)d_in[11];
    const float* w3 = (const float*)d_in[12]; const float* b3 = (const float*)d_in[13];
    const float* w4 = (const float*)d_in[14]; const float* b4 = (const float*)d_in[15];
    const float* w5 = (const float*)d_in[16]; const float* b5 = (const float*)d_in[17];
    const float* w6 = (const float*)d_in[18]; const float* b6 = (const float*)d_in[19];

    const int SM_CC = 33792 * 4;
    const int SM_CG = (RST + 16 * MV + 4 * MV + 256) * 4;

    cudaFuncSetAttribute(gemm_kernel,      cudaFuncAttributeMaxDynamicSharedMemorySize, SM_TOT);
    cudaFuncSetAttribute(crosscorr_kernel, cudaFuncAttributeMaxDynamicSharedMemorySize, SM_CC);
    cudaFuncSetAttribute(cg_kernel,        cudaFuncAttributeMaxDynamicSharedMemorySize, SM_CG);

    float* dA; cudaGetSymbolAddress((void**)&dA, g_dA);
    float* dB; cudaGetSymbolAddress((void**)&dB, g_dB);

    dim3 gv(64, 16);
    convert_kernel<<<gv, 256>>>(x1, x2);
    dim3 gg(2, 64);
    gemm_kernel<<<gg, 384, SM_TOT>>>();
    dim3 gc(16, 64);
    crosscorr_kernel<<<gc, 160, SM_CC>>>(x1, x2, y1, y2);
    fill_kernel<<<64, 256>>>();
    cg_kernel<<<32, 256, SM_CG>>>(0, d, alpha, reg, dA);
    cg_kernel<<<32, 256, SM_CG>>>(32, dA, alpha, reg, dB);
    head_kernel<<<32, 400>>>(beta, w1, b1, w2, b2, w3, b3, w4, b4, w5, b5, w6, b6,
                             (float*)d_out);
}

// round 17
// speedup vs baseline: 1.6286x; 1.3828x over previous
#include <cuda_runtime.h>
#include <math.h>

#define HW 16384
#define RST 20736   // 16*16*81
#define MV 400

__device__ float g_Rh[2][64 * RST];   // per-half autocorr partials
__device__ float g_P[64 * MV];
__device__ float g_dA[32 * MV];
__device__ float g_dB[32 * MV];

// ---------------- autocorr: CTA = (pair i<=j, sample s, h-half hb) -----------
// smem: xi 64x128, xj 72x136 (4-row halo, 4-col zero pad). 9 warps = one du.
// Partials (incl. mirror) stored with plain STG into g_Rh[hb].
__global__ __launch_bounds__(288) void autocorr_kernel(const float* __restrict__ x1,
                                                       const float* __restrict__ x2)
{
    extern __shared__ float sm[];
    float* xi = sm;          // 64*128 = 8192
    float* xj = sm + 8192;   // 72*136 = 9792
    const int s  = blockIdx.y;
    const int hb = blockIdx.z;
    const int h0 = hb * 64;
    const float* x = (s < 32) ? (x1 + (size_t)s * 16 * HW) : (x2 + (size_t)(s - 32) * 16 * HW);
    int i = 0, rem = blockIdx.x;
    while (rem >= 16 - i) { rem -= 16 - i; i++; }
    const int j = i + rem;
    const int tid = threadIdx.x;

    {
        const float4* gi = (const float4*)(x + (size_t)i * HW + (size_t)h0 * 128);
        for (int k = tid; k < 8192 / 4; k += 288) ((float4*)xi)[k] = gi[k];
        const float* gj = x + (size_t)j * HW;
        for (int k = tid; k < 72 * 34; k += 288) {
            int r = k / 34;
            int g = h0 + r - 4;
            int w0 = (k % 34) * 4 - 4;
            float t0 = 0.f, t1 = 0.f, t2 = 0.f, t3 = 0.f;
            if (g >= 0 && g < 128) {
                const float* row = gj + (size_t)g * 128;
                t0 = (w0 >= 0     && w0 < 128)     ? row[w0]     : 0.f;
                t1 = (w0 + 1 >= 0 && w0 + 1 < 128) ? row[w0 + 1] : 0.f;
                t2 = (w0 + 2 >= 0 && w0 + 2 < 128) ? row[w0 + 2] : 0.f;
                t3 = (w0 + 3 >= 0 && w0 + 3 < 128) ? row[w0 + 3] : 0.f;
            }
            ((float4*)xj)[k] = make_float4(t0, t1, t2, t3);
        }
    }
    __syncthreads();

    const int warp = tid >> 5, lane = tid & 31;
    const int w0 = lane << 2;
    float acc[9];
#pragma unroll
    for (int t = 0; t < 9; t++) acc[t] = 0.f;
    const float* pi = xi + w0;
    const float* pj = xj + warp * 136 + w0;
#pragma unroll 4
    for (int h = 0; h < 64; h++) {
        const float4 av = *(const float4*)pi;
        const float4 b0 = *(const float4*)pj;
        const float4 b1 = *(const float4*)(pj + 4);
        const float4 b2 = *(const float4*)(pj + 8);
        const float bb[12] = { b0.x, b0.y, b0.z, b0.w, b1.x, b1.y, b1.z, b1.w,
                               b2.x, b2.y, b2.z, b2.w };
#pragma unroll
        for (int t = 0; t < 9; t++) {
            acc[t] = fmaf(av.x, bb[t], acc[t]);
            acc[t] = fmaf(av.y, bb[t + 1], acc[t]);
            acc[t] = fmaf(av.z, bb[t + 2], acc[t]);
            acc[t] = fmaf(av.w, bb[t + 3], acc[t]);
        }
        pi += 128; pj += 136;
    }
    float* Rp = g_Rh[hb] + (size_t)s * RST;
#pragma unroll
    for (int t = 0; t < 9; t++) {
        float v = acc[t];
#pragma unroll
        for (int o = 16; o; o >>= 1) v += __shfl_down_sync(0xffffffffu, v, o);
        if (lane == 0) {
            Rp[(i * 16 + j) * 81 + warp * 9 + t] = v;
            if (i != j) Rp[(j * 16 + i) * 81 + (8 - warp) * 9 + (8 - t)] = v;
        }
    }
}

// ---------------- crosscorr: CTA = (channel j, sample s) ---------------------
__global__ __launch_bounds__(160) void crosscorr_kernel(const float* __restrict__ x1,
                                                        const float* __restrict__ x2,
                                                        const float* __restrict__ y1,
                                                        const float* __restrict__ y2)
{
    extern __shared__ float sm[];
    float* ys = sm;
    float* xs = sm + 16384;
    const int s = blockIdx.y, j = blockIdx.x;
    const float* x = (s < 32) ? (x1 + (size_t)s * 16 * HW) : (x2 + (size_t)(s - 32) * 16 * HW);
    const float* y = (s < 32) ? (y1 + (size_t)s * HW) : (y2 + (size_t)(s - 32) * HW);
    const int tid = threadIdx.x;
    {
        for (int k = tid; k < HW / 4; k += 160) ((float4*)ys)[k] = ((const float4*)y)[k];
        const float* gx = x + (size_t)j * HW;
        for (int k = tid; k < 128 * 34; k += 160) {
            int r = k / 34, w0 = (k % 34) * 4 - 4;
            float t0 = (w0 >= 0 && w0 < 128)         ? gx[r * 128 + w0]     : 0.f;
            float t1 = (w0 + 1 >= 0 && w0 + 1 < 128) ? gx[r * 128 + w0 + 1] : 0.f;
            float t2 = (w0 + 2 >= 0 && w0 + 2 < 128) ? gx[r * 128 + w0 + 2] : 0.f;
            float t3 = (w0 + 3 >= 0 && w0 + 3 < 128) ? gx[r * 128 + w0 + 3] : 0.f;
            ((float4*)xs)[k] = make_float4(t0, t1, t2, t3);
        }
    }
    __syncthreads();
    const int warp = tid >> 5, lane = tid & 31;
    const int du = warp - 2, w0 = lane << 2;
    float acc[5] = {0.f, 0.f, 0.f, 0.f, 0.f};
    const int hbeg = (du < 0) ? -du : 0;
    const int hend = (du > 0) ? 128 - du : 128;
    const float* py = ys + hbeg * 128 + w0;
    const float* px = xs + (hbeg + du) * 136 + w0;
    for (int h = hbeg; h < hend; h++) {
        const float4 av = *(const float4*)py;
        const float4 b0 = *(const float4*)px;
        const float4 b1 = *(const float4*)(px + 4);
        const float4 b2 = *(const float4*)(px + 8);
        const float bb[12] = { b0.x, b0.y, b0.z, b0.w, b1.x, b1.y, b1.z, b1.w,
                               b2.x, b2.y, b2.z, b2.w };
#pragma unroll
        for (int t = 0; t < 5; t++) {
            acc[t] = fmaf(av.x, bb[t + 2], acc[t]);
            acc[t] = fmaf(av.y, bb[t + 3], acc[t]);
            acc[t] = fmaf(av.z, bb[t + 4], acc[t]);
            acc[t] = fmaf(av.w, bb[t + 5], acc[t]);
        }
        py += 128; px += 136;
    }
#pragma unroll
    for (int t = 0; t < 5; t++) {
        float v = acc[t];
#pragma unroll
        for (int o = 16; o; o >>= 1) v += __shfl_down_sync(0xffffffffu, v, o);
        if (lane == 0) g_P[(size_t)s * MV + j * 25 + warp * 5 + t] = v;
    }
}

// ---------------- CG solve from R halves (Q never materialized) --------------
__device__ __forceinline__ float dot400(const float* A, const float* B, float* scr, int t)
{
    float v = 0.f;
    for (int k = t; k < MV; k += 256) v += A[k] * B[k];
#pragma unroll
    for (int o = 16; o; o >>= 1) v += __shfl_down_sync(0xffffffffu, v, o);
    if ((t & 31) == 0) scr[t >> 5] = v;
    __syncthreads();
    if (t < 32) {
        float w = (t < 8) ? scr[t] : 0.f;
#pragma unroll
        for (int o = 4; o; o >>= 1) w += __shfl_down_sync(0xffffffffu, w, o);
        if (t == 0) scr[0] = w;
    }
    __syncthreads();
    float r = scr[0];
    __syncthreads();
    return r;
}

__global__ __launch_bounds__(256) void cg_kernel(int soff, const float* __restrict__ dprev,
                                                 const float* __restrict__ alpha,
                                                 const float* __restrict__ reg,
                                                 float* __restrict__ dout)
{
    extern __shared__ float sm[];
    float* Rs  = sm;                 // 20736
    float* red = Rs + RST;           // 16*400
    float* vx  = red + 16 * MV;      // 400
    float* vr  = vx + MV;
    float* vp  = vr + MV;
    float* vq  = vp + MV;
    float* scr = vq + MV;            // 256
    const int s = blockIdx.x, t = threadIdx.x;
    const float a = alpha[s] * 16384.f * reg[0] / 400.f;

    {
        const float4* r0 = (const float4*)(g_Rh[0] + (size_t)(s + soff) * RST);
        const float4* r1 = (const float4*)(g_Rh[1] + (size_t)(s + soff) * RST);
        for (int k = t; k < RST / 4; k += 256) {
            float4 a0 = r0[k], a1 = r1[k];
            ((float4*)Rs)[k] = make_float4(a0.x + a1.x, a0.y + a1.y,
                                           a0.z + a1.z, a0.w + a1.w);
        }
    }
    for (int k = t; k < MV; k += 256) {
        float b = g_P[(size_t)(s + soff) * MV + k] + a * dprev[(size_t)s * MV + k];
        vr[k] = b; vp[k] = b; vx[k] = 0.f;
    }
    __syncthreads();
    float rs = dot400(vr, vr, scr, t);

    const int jj = t & 15;
    const float* Rb = Rs + t * 81;   // block (i = t>>4, j = t&15)

    for (int it = 0; it < 14; it++) {
        float vj[25];
#pragma unroll
        for (int o = 0; o < 25; o++) vj[o] = vp[jj * 25 + o];
        float acc[25];
#pragma unroll
        for (int o = 0; o < 25; o++) acc[o] = 0.f;
#pragma unroll
        for (int oi = 0; oi < 5; oi++)
#pragma unroll
            for (int oj = 0; oj < 5; oj++) {
                const float v = vj[oi * 5 + oj];
#pragma unroll
                for (int p = 0; p < 5; p++)
#pragma unroll
                    for (int q = 0; q < 5; q++)
                        acc[p * 5 + q] = fmaf(Rb[(4 + oi - p) * 9 + (4 + oj - q)], v, acc[p * 5 + q]);
            }
#pragma unroll
        for (int o = 0; o < 25; o++) red[jj * MV + (t >> 4) * 25 + o] = acc[o];
        __syncthreads();
        for (int k = t; k < MV; k += 256) {
            float ssum = a * vp[k];
#pragma unroll
            for (int j2 = 0; j2 < 16; j2++) ssum += red[j2 * MV + k];
            vq[k] = ssum;
        }
        __syncthreads();
        float pq = dot400(vp, vq, scr, t);
        float al = rs / pq;
        for (int k = t; k < MV; k += 256) { vx[k] += al * vp[k]; vr[k] -= al * vq[k]; }
        __syncthreads();
        float rs2 = dot400(vr, vr, scr, t);
        float be = rs2 / rs;
        rs = rs2;
        for (int k = t; k < MV; k += 256) vp[k] = vr[k] + be * vp[k];
        __syncthreads();
    }
    for (int k = t; k < MV; k += 256) dout[(size_t)s * MV + k] = vx[k];
}

// ---------------- conv head: 6 x conv3x3(pad1) on 5x5 maps -------------------
__device__ __forceinline__ void conv5(float* outb, const float* inb, const float* w,
                                      const float* bias, int cin, int doRelu, int t)
{
    if (t < MV) {
        const int oc = t / 25, pos = t % 25, p = pos / 5, q = pos % 5;
        float v = bias[oc];
        for (int ic = 0; ic < cin; ic++) {
            const float* wp = w + (oc * cin + ic) * 9;
            const float* ip = inb + ic * 25;
#pragma unroll
            for (int kh = 0; kh < 3; kh++) {
                int r = p + kh - 1;
                if (r < 0 || r > 4) continue;
#pragma unroll
                for (int kw = 0; kw < 3; kw++) {
                    int c = q + kw - 1;
                    if (c < 0 || c > 4) continue;
                    v = fmaf(wp[kh * 3 + kw], ip[r * 5 + c], v);
                }
            }
        }
        outb[t] = doRelu ? fmaxf(v, 0.f) : v;
    }
    __syncthreads();
}

__global__ __launch_bounds__(400) void head_kernel(const float* __restrict__ beta,
    const float* w1, const float* b1, const float* w2, const float* b2,
    const float* w3, const float* b3, const float* w4, const float* b4,
    const float* w5, const float* b5, const float* w6, const float* b6,
    float* __restrict__ out)
{
    __shared__ float h0[17 * 25], bA[16 * 25], bB[16 * 25];
    const int s = blockIdx.x, t = threadIdx.x;
    if (t < MV) h0[t] = g_dB[(size_t)s * MV + t];
    if (t < 25) h0[MV + t] = 1.0f / sqrtf(beta[s]);
    __syncthreads();
    conv5(bA, h0, w1, b1, 17, 1, t);
    conv5(bB, bA, w2, b2, 16, 1, t);
    conv5(bA, bB, w3, b3, 16, 1, t);
    conv5(bB, bA, w4, b4, 16, 1, t);
    conv5(bA, bB, w5, b5, 16, 1, t);
    if (t < MV) {
        const int oc = t / 25, pos = t % 25, p = pos / 5, q = pos % 5;
        float v = b6[oc];
        for (int ic = 0; ic < 16; ic++) {
            const float* wp = w6 + (oc * 16 + ic) * 9;
            const float* ip = bA + ic * 25;
#pragma unroll
            for (int kh = 0; kh < 3; kh++) {
                int r = p + kh - 1;
                if (r < 0 || r > 4) continue;
#pragma unroll
                for (int kw = 0; kw < 3; kw++) {
                    int c = q + kw - 1;
                    if (c < 0 || c > 4) continue;
                    v = fmaf(wp[kh * 3 + kw], ip[r * 5 + c], v);
                }
            }
        }
        out[(size_t)s * MV + t] = v + h0[t];
    }
}

extern "C" void kernel_launch(void* const* d_in, const int* in_sizes, int n_in,
                              void* d_out, int out_size)
{
    const float* x1 = (const float*)d_in[0];
    const float* x2 = (const float*)d_in[1];
    const float* d  = (const float*)d_in[2];
    const float* y1 = (const float*)d_in[3];
    const float* y2 = (const float*)d_in[4];
    const float* alpha = (const float*)d_in[5];
    const float* beta  = (const float*)d_in[6];
    const float* reg   = (const float*)d_in[7];
    const float* w1 = (const float*)d_in[8];  const float* b1 = (const float*)d_in[9];
    const float* w2 = (const float*)d_in[10]; const float* b2 = (const float*)d_in[11];
    const float* w3 = (const float*)d_in[12]; const float* b3 = (const float*)d_in[13];
    const float* w4 = (const float*)d_in[14]; const float* b4 = (const float*)d_in[15];
    const float* w5 = (const float*)d_in[16]; const float* b5 = (const float*)d_in[17];
    const float* w6 = (const float*)d_in[18]; const float* b6 = (const float*)d_in[19];

    const int SM_AC = (8192 + 72 * 136) * 4;               // 71,936 B
    const int SM_CC = 33792 * 4;                           // 135,168 B
    const int SM_CG = (RST + 16 * MV + 4 * MV + 256) * 4;  // ~115 KB

    cudaFuncSetAttribute(autocorr_kernel,  cudaFuncAttributeMaxDynamicSharedMemorySize, SM_AC);
    cudaFuncSetAttribute(crosscorr_kernel, cudaFuncAttributeMaxDynamicSharedMemorySize, SM_CC);
    cudaFuncSetAttribute(cg_kernel,        cudaFuncAttributeMaxDynamicSharedMemorySize, SM_CG);

    float* dA; cudaGetSymbolAddress((void**)&dA, g_dA);
    float* dB; cudaGetSymbolAddress((void**)&dB, g_dB);

    dim3 ga(136, 64, 2);
    autocorr_kernel<<<ga, 288, SM_AC>>>(x1, x2);
    dim3 gc(16, 64);
    crosscorr_kernel<<<gc, 160, SM_CC>>>(x1, x2, y1, y2);
    cg_kernel<<<32, 256, SM_CG>>>(0, d, alpha, reg, dA);
    cg_kernel<<<32, 256, SM_CG>>>(32, dA, alpha, reg, dB);
    head_kernel<<<32, 400>>>(beta, w1, b1, w2, b2, w3, b3, w4, b4, w5, b5, w6, b6,
                             (float*)d_out);
}